// round 4
// baseline (speedup 1.0000x reference)
#include <cuda_runtime.h>

#define FP      80
#define MTAPS   24
#define NSTAGES 20
#define BATCH   8
#define NFRAMES 1024
#define TLEN    (NFRAMES * FP)        // 81920

#define RPT     4                     // 4 | 80 -> thread never crosses a frame
#define BLOCK   512
#define WINW    (BLOCK * RPT)         // 2048
#define HALO    (NSTAGES * MTAPS)     // 480
#define TBOUT   (WINW - HALO)         // 1568
#define PADZ    24
#define BPB     ((TLEN + TBOUT - 1) / TBOUT)   // 53

typedef unsigned long long u64p;

__device__ __forceinline__ u64p pk2(float lo, float hi) {
    u64p r; asm("mov.b64 %0, {%1, %2};" : "=l"(r) : "f"(lo), "f"(hi)); return r;
}
__device__ __forceinline__ void upk2(u64p v, float& lo, float& hi) {
    asm("mov.b64 {%0, %1}, %2;" : "=f"(lo), "=f"(hi) : "l"(v));
}
__device__ __forceinline__ u64p ffma2(u64p a, u64p b, u64p c) {
    u64p d; asm("fma.rn.f32x2 %0, %1, %2, %3;" : "=l"(d) : "l"(a), "l"(b), "l"(c)); return d;
}

__global__ void __launch_bounds__(BLOCK, 1)
fir_taylor_kernel(const float* __restrict__ x,
                  const float* __restrict__ mc,
                  const float* __restrict__ a,
                  const float* __restrict__ wts,
                  float* __restrict__ out)
{
    // Duplicated-pair stage buffers: entry p holds (v_p, v_p) as one u64.
    __shared__ __align__(16) u64p d0[WINW + PADZ];
    __shared__ __align__(16) u64p d1[WINW + PADZ];
    __shared__ float s_a[NSTAGES + 1];
    __shared__ float s_w[NSTAGES + 1];

    const int tid = threadIdx.x;
    const int blk = blockIdx.x;
    const int b   = blk / BPB;
    const int tb  = blk % BPB;
    const int t0  = tb * TBOUT;
    const int g0  = t0 - HALO;

    if (tid <= NSTAGES) { s_a[tid] = a[tid]; s_w[tid] = wts[tid]; }
    if (tid < PADZ)     { d0[tid] = 0ULL; d1[tid] = 0ULL; }

    const int lp    = tid * RPT;
    const int tbase = g0 + lp;

    // Load own 4 samples (coalesced), publish duplicated pairs
    const float* xb = x + b * TLEN;
    float xv[RPT];
#pragma unroll
    for (int r = 0; r < RPT; r++) {
        int t = tbase + r;
        xv[r] = (t >= 0 && t < TLEN) ? __ldg(xb + t) : 0.0f;
    }
    {
        u64p p0 = pk2(xv[0], xv[0]), p1 = pk2(xv[1], xv[1]);
        u64p p2 = pk2(xv[2], xv[2]), p3 = pk2(xv[3], xv[3]);
        ulonglong2* st = (ulonglong2*)(d0 + PADZ + lp);
        st[0] = make_ulonglong2(p0, p1);
        st[1] = make_ulonglong2(p2, p3);
    }

    // ---- stage-invariant packed coefficients: kj = (cc_j, dp_j) ----
    int tc = tbase < 0 ? 0 : (tbase >= TLEN ? TLEN - 1 : tbase);
    int n  = tc / FP;
    int n1 = (n + 1 < NFRAMES) ? n + 1 : NFRAMES - 1;
    const float invP = 1.0f / (float)FP;
    const float w0   = (float)(tc - n * FP) * invP;

    const float* mrow0 = mc + ((long)b * NFRAMES + n)  * (MTAPS + 1);
    const float* mrow1 = mc + ((long)b * NFRAMES + n1) * (MTAPS + 1);

    u64p kj[MTAPS];
#pragma unroll
    for (int j = 0; j < MTAPS; j++) {
        float c0v = mrow0[j + 1];
        float d   = mrow1[j + 1] - c0v;
        kj[j] = pk2(fmaf(w0, d, c0v), d * invP);   // (coef@r0, per-sample delta)
    }
    const float k0 = mrow0[0];
    const float dk = mrow1[0] - k0;

    __syncthreads();

    float y[RPT];
    {
        const float a0 = s_a[0];
#pragma unroll
        for (int r = 0; r < RPT; r++) y[r] = xv[r] * a0;
    }

    // Own duplicated pairs, carried in registers across stages
    u64p od[RPT];
#pragma unroll
    for (int r = 0; r < RPT; r++) od[r] = pk2(xv[r], xv[r]);

    u64p* cur = d0;
    u64p* nxt = d1;

    for (int i = 1; i <= NSTAGES; i++) {
        const float wgt = s_w[i];
        const float ai  = s_a[i];

        // Window pairs W[0..27]: W[k] = (v_{lp-24+k}, same). Halo from smem, own from regs.
        u64p W[MTAPS + RPT];
        {
            const ulonglong2* v = (const ulonglong2*)(cur + PADZ + lp - MTAPS);
#pragma unroll
            for (int q = 0; q < MTAPS / 2; q++) {
                ulonglong2 u = v[q];
                W[2*q] = u.x; W[2*q + 1] = u.y;
            }
        }
#pragma unroll
        for (int r = 0; r < RPT; r++) W[MTAPS + r] = od[r];

        // Per output r: AB = (A, B) = sum_j W[24+r-j] * (cc_j, dp_j)
        float acc[RPT];
#pragma unroll
        for (int r = 0; r < RPT; r++) {
            u64p ab = 0ULL;
#pragma unroll
            for (int j = 1; j <= MTAPS; j++)
                ab = ffma2(W[MTAPS + r - j], kj[j - 1], ab);
            float A, B;
            upk2(ab, A, B);
            float s = fmaf((float)r, B, A) * wgt;   // coef(r) = cc + r*dp
            acc[r] = s;
            y[r]   = fmaf(s, ai, y[r]);
        }

#pragma unroll
        for (int r = 0; r < RPT; r++) od[r] = pk2(acc[r], acc[r]);

        if (i < NSTAGES) {
            ulonglong2* st = (ulonglong2*)(nxt + PADZ + lp);
            st[0] = make_ulonglong2(od[0], od[1]);
            st[1] = make_ulonglong2(od[2], od[3]);
            __syncthreads();
            u64p* tmp = cur; cur = nxt; nxt = tmp;
        }
    }

    // ---- epilogue: out = y * exp(interp(mc[...,0])) ----
    if (lp >= HALO) {
        float* ob = out + b * TLEN;
#pragma unroll
        for (int r = 0; r < RPT; r++) {
            int tt = tbase + r;
            if (tt < TLEN) {
                float K = expf(fmaf(fmaf((float)r, invP, w0), dk, k0));
                ob[tt] = y[r] * K;
            }
        }
    }
}

extern "C" void kernel_launch(void* const* d_in, const int* in_sizes, int n_in,
                              void* d_out, int out_size)
{
    (void)in_sizes; (void)n_in; (void)out_size;
    const float* x   = (const float*)d_in[0];
    const float* mc  = (const float*)d_in[1];
    const float* a   = (const float*)d_in[2];
    const float* wts = (const float*)d_in[3];
    float* out = (float*)d_out;

    fir_taylor_kernel<<<BATCH * BPB, BLOCK>>>(x, mc, a, wts, out);
}

// round 5
// speedup vs baseline: 1.6145x; 1.6145x over previous
#include <cuda_runtime.h>

#define FP      80
#define MTAPS   24
#define NSTAGES 20
#define BATCH   8
#define NFRAMES 1024
#define TLEN    (NFRAMES * FP)        // 81920

#define RPT     4                     // 4 | 80 -> thread never crosses a frame
#define BLOCK   512
#define WINW    (BLOCK * RPT)         // 2048
#define HALO    (NSTAGES * MTAPS)     // 480
#define TBOUT   (WINW - HALO)         // 1568
#define PADZ    24
#define BPB     ((TLEN + TBOUT - 1) / TBOUT)   // 53

typedef unsigned long long u64p;

__device__ __forceinline__ u64p pk2(float lo, float hi) {
    u64p r; asm("mov.b64 %0, {%1, %2};" : "=l"(r) : "f"(lo), "f"(hi)); return r;
}
__device__ __forceinline__ void upk2(u64p v, float& lo, float& hi) {
    asm("mov.b64 {%0, %1}, %2;" : "=f"(lo), "=f"(hi) : "l"(v));
}
__device__ __forceinline__ u64p ffma2(u64p a, u64p b, u64p c) {
    u64p d; asm("fma.rn.f32x2 %0, %1, %2, %3;" : "=l"(d) : "l"(a), "l"(b), "l"(c)); return d;
}
__device__ __forceinline__ u64p dup2(float v) { return pk2(v, v); }

__global__ void __launch_bounds__(BLOCK, 1)
fir_taylor_kernel(const float* __restrict__ x,
                  const float* __restrict__ mc,
                  const float* __restrict__ a,
                  const float* __restrict__ wts,
                  float* __restrict__ out)
{
    __shared__ float buf0[WINW + PADZ];
    __shared__ float buf1[WINW + PADZ];
    __shared__ float s_f[NSTAGES + 1];   // a[i] * prod_{k<=i} wts[k]

    const int tid = threadIdx.x;
    const int blk = blockIdx.x;
    const int b   = blk / BPB;
    const int tb  = blk % BPB;
    const int t0  = tb * TBOUT;
    const int g0  = t0 - HALO;

    if (tid == 0) {
        float P = 1.0f;
        s_f[0] = a[0];
        for (int i = 1; i <= NSTAGES; i++) { P *= wts[i]; s_f[i] = a[i] * P; }
    }
    if (tid < PADZ) { buf0[tid] = 0.0f; buf1[tid] = 0.0f; }

    const int lp    = tid * RPT;
    const int tbase = g0 + lp;

    // own 4 samples -> regs + smem
    const float* xb = x + b * TLEN;
    float acc0, acc1, acc2, acc3;
    {
        int t = tbase;
        acc0 = (t + 0 >= 0 && t + 0 < TLEN) ? __ldg(xb + t + 0) : 0.0f;
        acc1 = (t + 1 >= 0 && t + 1 < TLEN) ? __ldg(xb + t + 1) : 0.0f;
        acc2 = (t + 2 >= 0 && t + 2 < TLEN) ? __ldg(xb + t + 2) : 0.0f;
        acc3 = (t + 3 >= 0 && t + 3 < TLEN) ? __ldg(xb + t + 3) : 0.0f;
        float4 st; st.x = acc0; st.y = acc1; st.z = acc2; st.w = acc3;
        *((float4*)(buf0 + PADZ + lp)) = st;
    }

    // ---- stage-invariant packed coefficients kj = (cc_j, dp_j) ----
    int tc = tbase < 0 ? 0 : (tbase >= TLEN ? TLEN - 1 : tbase);
    int n  = tc / FP;
    int n1 = (n + 1 < NFRAMES) ? n + 1 : NFRAMES - 1;
    const float invP = 1.0f / (float)FP;
    const float w0   = (float)(tc - n * FP) * invP;

    const float* mrow0 = mc + ((long)b * NFRAMES + n)  * (MTAPS + 1);
    const float* mrow1 = mc + ((long)b * NFRAMES + n1) * (MTAPS + 1);

    u64p kj[MTAPS];
#pragma unroll
    for (int j = 0; j < MTAPS; j++) {
        float c0v = mrow0[j + 1];
        float d   = mrow1[j + 1] - c0v;
        kj[j] = pk2(fmaf(w0, d, c0v), d * invP);
    }
    const float k0 = mrow0[0];
    const float dk = mrow1[0] - k0;

    __syncthreads();

    float y0 = acc0 * s_f[0], y1 = acc1 * s_f[0], y2 = acc2 * s_f[0], y3 = acc3 * s_f[0];

    float* cur = buf0;
    float* nxt = buf1;

#pragma unroll 1
    for (int i = 1; i <= NSTAGES; i++) {
        const float fi = s_f[i];

        // halo scalars w[0..23] = cur[lp-24 .. lp-1] (16B-aligned vec4 loads)
        float w[MTAPS];
        {
            const float4* v = (const float4*)(cur + PADZ + lp - MTAPS);
#pragma unroll
            for (int q = 0; q < MTAPS / 4; q++) {
                float4 f = v[q];
                w[4*q+0] = f.x; w[4*q+1] = f.y; w[4*q+2] = f.z; w[4*q+3] = f.w;
            }
        }

        // (A,B) accumulators per output r; window dups rotate (1 new dup per tap)
        u64p ab0 = 0ULL, ab1 = 0ULL, ab2 = 0ULL, ab3 = 0ULL;
        u64p d0 = dup2(w[23]);   // w[24-j] at j=1
        u64p d1 = dup2(acc0);    // w[25-j] at j=1
        u64p d2 = dup2(acc1);
        u64p d3 = dup2(acc2);
#pragma unroll
        for (int j = 1; j <= MTAPS; j++) {
            u64p k = kj[j - 1];
            ab0 = ffma2(d0, k, ab0);
            ab1 = ffma2(d1, k, ab1);
            ab2 = ffma2(d2, k, ab2);
            ab3 = ffma2(d3, k, ab3);
            d3 = d2; d2 = d1; d1 = d0;
            if (j < MTAPS) d0 = dup2(w[23 - j]);
        }

        float A, B;
        upk2(ab0, A, B); acc0 = A;                     // s(0) = A
        upk2(ab1, A, B); acc1 = fmaf(1.0f, B, A);
        upk2(ab2, A, B); acc2 = fmaf(2.0f, B, A);
        upk2(ab3, A, B); acc3 = fmaf(3.0f, B, A);

        y0 = fmaf(acc0, fi, y0);
        y1 = fmaf(acc1, fi, y1);
        y2 = fmaf(acc2, fi, y2);
        y3 = fmaf(acc3, fi, y3);

        if (i < NSTAGES) {
            float4 st; st.x = acc0; st.y = acc1; st.z = acc2; st.w = acc3;
            *((float4*)(nxt + PADZ + lp)) = st;
            __syncthreads();
            float* tmp = cur; cur = nxt; nxt = tmp;
        }
    }

    // ---- epilogue: out = y * exp(interp(mc[...,0])) ----
    if (lp >= HALO) {
        float* ob = out + b * TLEN;
        float yv[RPT] = { y0, y1, y2, y3 };
#pragma unroll
        for (int r = 0; r < RPT; r++) {
            int tt = tbase + r;
            if (tt < TLEN) {
                float K = expf(fmaf(fmaf((float)r, invP, w0), dk, k0));
                ob[tt] = yv[r] * K;
            }
        }
    }
}

extern "C" void kernel_launch(void* const* d_in, const int* in_sizes, int n_in,
                              void* d_out, int out_size)
{
    (void)in_sizes; (void)n_in; (void)out_size;
    const float* x   = (const float*)d_in[0];
    const float* mc  = (const float*)d_in[1];
    const float* a   = (const float*)d_in[2];
    const float* wts = (const float*)d_in[3];
    float* out = (float*)d_out;

    fir_taylor_kernel<<<BATCH * BPB, BLOCK>>>(x, mc, a, wts, out);
}

// round 6
// speedup vs baseline: 1.7048x; 1.0559x over previous
#include <cuda_runtime.h>

#define FP      80
#define MTAPS   24
#define NSTAGES 20
#define BATCH   8
#define NFRAMES 1024
#define TLEN    (NFRAMES * FP)        // 81920

#define RPT     8                     // 8 | 80 -> thread never crosses a frame
#define BLOCK   256
#define WINW    (BLOCK * RPT)         // 2048
#define HALO    (NSTAGES * MTAPS)     // 480
#define TBOUT   (WINW - HALO)         // 1568
#define PADZ    24
#define BPB     ((TLEN + TBOUT - 1) / TBOUT)   // 53

typedef unsigned long long u64p;

__device__ __forceinline__ u64p pk2(float lo, float hi) {
    u64p r; asm("mov.b64 %0, {%1, %2};" : "=l"(r) : "f"(lo), "f"(hi)); return r;
}
__device__ __forceinline__ void upk2(u64p v, float& lo, float& hi) {
    asm("mov.b64 {%0, %1}, %2;" : "=f"(lo), "=f"(hi) : "l"(v));
}
__device__ __forceinline__ u64p ffma2(u64p a, u64p b, u64p c) {
    u64p d; asm("fma.rn.f32x2 %0, %1, %2, %3;" : "=l"(d) : "l"(a), "l"(b), "l"(c)); return d;
}
__device__ __forceinline__ u64p dup2(float v) { return pk2(v, v); }

__global__ void __launch_bounds__(BLOCK, 2)
fir_taylor_kernel(const float* __restrict__ x,
                  const float* __restrict__ mc,
                  const float* __restrict__ a,
                  const float* __restrict__ wts,
                  float* __restrict__ out)
{
    __shared__ float buf0[WINW + PADZ];
    __shared__ float buf1[WINW + PADZ];
    __shared__ float s_f[NSTAGES + 1];   // a[i] * prod_{k<=i} wts[k]

    const int tid = threadIdx.x;
    const int blk = blockIdx.x;
    const int b   = blk / BPB;
    const int tb  = blk % BPB;
    const int t0  = tb * TBOUT;
    const int g0  = t0 - HALO;

    if (tid == 0) {
        float P = 1.0f;
        s_f[0] = a[0];
        for (int i = 1; i <= NSTAGES; i++) { P *= wts[i]; s_f[i] = a[i] * P; }
    }
    if (tid < PADZ) { buf0[tid] = 0.0f; buf1[tid] = 0.0f; }

    const int lp    = tid * RPT;
    const int tbase = g0 + lp;

    // own 8 samples -> regs + smem
    const float* xb = x + b * TLEN;
    float acc[RPT];
#pragma unroll
    for (int r = 0; r < RPT; r++) {
        int t = tbase + r;
        acc[r] = (t >= 0 && t < TLEN) ? __ldg(xb + t) : 0.0f;
    }
    {
        float4* st = (float4*)(buf0 + PADZ + lp);
        float4 f0; f0.x = acc[0]; f0.y = acc[1]; f0.z = acc[2]; f0.w = acc[3];
        float4 f1; f1.x = acc[4]; f1.y = acc[5]; f1.z = acc[6]; f1.w = acc[7];
        st[0] = f0; st[1] = f1;
    }

    // ---- stage-invariant packed coefficients kj = (cc_j, dp_j) ----
    int tc = tbase < 0 ? 0 : (tbase >= TLEN ? TLEN - 1 : tbase);
    int n  = tc / FP;
    int n1 = (n + 1 < NFRAMES) ? n + 1 : NFRAMES - 1;
    const float invP = 1.0f / (float)FP;
    const float w0   = (float)(tc - n * FP) * invP;

    const float* mrow0 = mc + ((long)b * NFRAMES + n)  * (MTAPS + 1);
    const float* mrow1 = mc + ((long)b * NFRAMES + n1) * (MTAPS + 1);

    u64p kj[MTAPS];
#pragma unroll
    for (int j = 0; j < MTAPS; j++) {
        float c0v = mrow0[j + 1];
        float d   = mrow1[j + 1] - c0v;
        kj[j] = pk2(fmaf(w0, d, c0v), d * invP);
    }
    const float k0 = mrow0[0];
    const float dk = mrow1[0] - k0;

    __syncthreads();

    float y[RPT];
    {
        const float f0 = s_f[0];
#pragma unroll
        for (int r = 0; r < RPT; r++) y[r] = acc[r] * f0;
    }

    float* cur = buf0;
    float* nxt = buf1;

#pragma unroll 1
    for (int i = 1; i <= NSTAGES; i++) {
        const float fi = s_f[i];

        // halo w[0..23] = cur[lp-24 .. lp-1]
        float w[MTAPS];
        {
            const float4* v = (const float4*)(cur + PADZ + lp - MTAPS);
#pragma unroll
            for (int q = 0; q < MTAPS / 4; q++) {
                float4 f = v[q];
                w[4*q+0] = f.x; w[4*q+1] = f.y; w[4*q+2] = f.z; w[4*q+3] = f.w;
            }
        }

        float na[RPT];

        // ---- group A: outputs r = 0..3 ; window base index 24 (w[24..27]=acc[0..3])
        {
            u64p ab0 = 0ULL, ab1 = 0ULL, ab2 = 0ULL, ab3 = 0ULL;
            u64p d0 = dup2(w[23]);
            u64p d1 = dup2(acc[0]);
            u64p d2 = dup2(acc[1]);
            u64p d3 = dup2(acc[2]);
#pragma unroll
            for (int j = 1; j <= MTAPS; j++) {
                u64p k = kj[j - 1];
                ab0 = ffma2(d0, k, ab0);
                ab1 = ffma2(d1, k, ab1);
                ab2 = ffma2(d2, k, ab2);
                ab3 = ffma2(d3, k, ab3);
                d3 = d2; d2 = d1; d1 = d0;
                if (j < MTAPS) d0 = dup2(w[23 - j]);
            }
            float A, B;
            upk2(ab0, A, B); na[0] = A;
            upk2(ab1, A, B); na[1] = fmaf(1.0f, B, A);
            upk2(ab2, A, B); na[2] = fmaf(2.0f, B, A);
            upk2(ab3, A, B); na[3] = fmaf(3.0f, B, A);
        }

        // ---- group B: outputs r = 4..7 ; window base 28 (w[28..31]=acc[4..7])
        {
            u64p ab0 = 0ULL, ab1 = 0ULL, ab2 = 0ULL, ab3 = 0ULL;
            u64p d0 = dup2(acc[3]);   // idx 27
            u64p d1 = dup2(acc[4]);
            u64p d2 = dup2(acc[5]);
            u64p d3 = dup2(acc[6]);
#pragma unroll
            for (int j = 1; j <= MTAPS; j++) {
                u64p k = kj[j - 1];
                ab0 = ffma2(d0, k, ab0);
                ab1 = ffma2(d1, k, ab1);
                ab2 = ffma2(d2, k, ab2);
                ab3 = ffma2(d3, k, ab3);
                d3 = d2; d2 = d1; d1 = d0;
                if (j < MTAPS) {
                    int idx = 27 - j;     // next window element for chain 0
                    d0 = (idx >= 24) ? dup2(acc[idx - 24]) : dup2(w[idx]);
                }
            }
            float A, B;
            upk2(ab0, A, B); na[4] = fmaf(4.0f, B, A);
            upk2(ab1, A, B); na[5] = fmaf(5.0f, B, A);
            upk2(ab2, A, B); na[6] = fmaf(6.0f, B, A);
            upk2(ab3, A, B); na[7] = fmaf(7.0f, B, A);
        }

#pragma unroll
        for (int r = 0; r < RPT; r++) {
            acc[r] = na[r];
            y[r]   = fmaf(na[r], fi, y[r]);
        }

        if (i < NSTAGES) {
            float4* st = (float4*)(nxt + PADZ + lp);
            float4 f0; f0.x = acc[0]; f0.y = acc[1]; f0.z = acc[2]; f0.w = acc[3];
            float4 f1; f1.x = acc[4]; f1.y = acc[5]; f1.z = acc[6]; f1.w = acc[7];
            st[0] = f0; st[1] = f1;
            __syncthreads();
            float* tmp = cur; cur = nxt; nxt = tmp;
        }
    }

    // ---- epilogue: out = y * exp(interp(mc[...,0])) ----
    if (lp >= HALO) {
        float* ob = out + b * TLEN;
#pragma unroll
        for (int r = 0; r < RPT; r++) {
            int tt = tbase + r;
            if (tt < TLEN) {
                float K = expf(fmaf(fmaf((float)r, invP, w0), dk, k0));
                ob[tt] = y[r] * K;
            }
        }
    }
}

extern "C" void kernel_launch(void* const* d_in, const int* in_sizes, int n_in,
                              void* d_out, int out_size)
{
    (void)in_sizes; (void)n_in; (void)out_size;
    const float* x   = (const float*)d_in[0];
    const float* mc  = (const float*)d_in[1];
    const float* a   = (const float*)d_in[2];
    const float* wts = (const float*)d_in[3];
    float* out = (float*)d_out;

    fir_taylor_kernel<<<BATCH * BPB, BLOCK>>>(x, mc, a, wts, out);
}

// round 7
// speedup vs baseline: 1.9071x; 1.1187x over previous
#include <cuda_runtime.h>

#define FP      80
#define MTAPS   24
#define NSTAGES 20
#define BATCH   8
#define NFRAMES 1024
#define TLEN    (NFRAMES * FP)        // 81920

#define RPT     8                     // 8 | 80 -> thread never crosses a frame
#define BLOCK   640                   // 20 warps
#define WINW    (BLOCK * RPT)         // 5120
#define HALO    (NSTAGES * MTAPS)     // 480
#define TBOUT   (WINW - HALO)         // 4640 (multiple of 16 -> alignment holds)
#define PADZ    24
#define BPB     ((TLEN + TBOUT - 1) / TBOUT)   // 18  -> grid 144 = ONE wave

typedef unsigned long long u64p;

__device__ __forceinline__ u64p pk2(float lo, float hi) {
    u64p r; asm("mov.b64 %0, {%1, %2};" : "=l"(r) : "f"(lo), "f"(hi)); return r;
}
__device__ __forceinline__ void upk2(u64p v, float& lo, float& hi) {
    asm("mov.b64 {%0, %1}, %2;" : "=f"(lo), "=f"(hi) : "l"(v));
}
__device__ __forceinline__ u64p ffma2(u64p a, u64p b, u64p c) {
    u64p d; asm("fma.rn.f32x2 %0, %1, %2, %3;" : "=l"(d) : "l"(a), "l"(b), "l"(c)); return d;
}
__device__ __forceinline__ u64p dup2(float v) { return pk2(v, v); }

__global__ void __launch_bounds__(BLOCK, 1)
fir_taylor_kernel(const float* __restrict__ x,
                  const float* __restrict__ mc,
                  const float* __restrict__ a,
                  const float* __restrict__ wts,
                  float* __restrict__ out)
{
    __shared__ float buf0[WINW + PADZ];
    __shared__ float buf1[WINW + PADZ];
    __shared__ float s_f[NSTAGES + 1];   // a[i] * prod_{k<=i} wts[k]

    const int tid = threadIdx.x;
    const int blk = blockIdx.x;
    const int b   = blk / BPB;
    const int tb  = blk % BPB;
    const int t0  = tb * TBOUT;
    const int g0  = t0 - HALO;

    if (tid == 0) {
        float P = 1.0f;
        s_f[0] = a[0];
        for (int i = 1; i <= NSTAGES; i++) { P *= wts[i]; s_f[i] = a[i] * P; }
    }
    if (tid < PADZ) { buf0[tid] = 0.0f; buf1[tid] = 0.0f; }

    const int lp    = tid * RPT;
    const int tbase = g0 + lp;

    // own 8 samples -> regs + smem
    const float* xb = x + b * TLEN;
    float acc[RPT];
#pragma unroll
    for (int r = 0; r < RPT; r++) {
        int t = tbase + r;
        acc[r] = (t >= 0 && t < TLEN) ? __ldg(xb + t) : 0.0f;
    }
    {
        float4* st = (float4*)(buf0 + PADZ + lp);
        float4 f0; f0.x = acc[0]; f0.y = acc[1]; f0.z = acc[2]; f0.w = acc[3];
        float4 f1; f1.x = acc[4]; f1.y = acc[5]; f1.z = acc[6]; f1.w = acc[7];
        st[0] = f0; st[1] = f1;
    }

    // ---- stage-invariant packed coefficients kj = (cc_j, dp_j) ----
    int tc = tbase < 0 ? 0 : (tbase >= TLEN ? TLEN - 1 : tbase);
    int n  = tc / FP;
    int n1 = (n + 1 < NFRAMES) ? n + 1 : NFRAMES - 1;
    const float invP = 1.0f / (float)FP;
    const float w0   = (float)(tc - n * FP) * invP;

    const float* mrow0 = mc + ((long)b * NFRAMES + n)  * (MTAPS + 1);
    const float* mrow1 = mc + ((long)b * NFRAMES + n1) * (MTAPS + 1);

    u64p kj[MTAPS];
#pragma unroll
    for (int j = 0; j < MTAPS; j++) {
        float c0v = mrow0[j + 1];
        float d   = mrow1[j + 1] - c0v;
        kj[j] = pk2(fmaf(w0, d, c0v), d * invP);
    }
    const float k0 = mrow0[0];
    const float dk = mrow1[0] - k0;

    __syncthreads();

    float y[RPT];
    {
        const float f0 = s_f[0];
#pragma unroll
        for (int r = 0; r < RPT; r++) y[r] = acc[r] * f0;
    }

    float* cur = buf0;
    float* nxt = buf1;

#pragma unroll 1
    for (int i = 1; i <= NSTAGES; i++) {
        const float fi = s_f[i];

        // halo w[0..23] = cur[lp-24 .. lp-1]
        float w[MTAPS];
        {
            const float4* v = (const float4*)(cur + PADZ + lp - MTAPS);
#pragma unroll
            for (int q = 0; q < MTAPS / 4; q++) {
                float4 f = v[q];
                w[4*q+0] = f.x; w[4*q+1] = f.y; w[4*q+2] = f.z; w[4*q+3] = f.w;
            }
        }

        float na[RPT];

        // ---- group A: outputs r = 0..3 (window w[24..27] = acc[0..3])
        {
            u64p ab0 = 0ULL, ab1 = 0ULL, ab2 = 0ULL, ab3 = 0ULL;
            u64p d0 = dup2(w[23]);
            u64p d1 = dup2(acc[0]);
            u64p d2 = dup2(acc[1]);
            u64p d3 = dup2(acc[2]);
#pragma unroll
            for (int j = 1; j <= MTAPS; j++) {
                u64p k = kj[j - 1];
                ab0 = ffma2(d0, k, ab0);
                ab1 = ffma2(d1, k, ab1);
                ab2 = ffma2(d2, k, ab2);
                ab3 = ffma2(d3, k, ab3);
                d3 = d2; d2 = d1; d1 = d0;
                if (j < MTAPS) d0 = dup2(w[23 - j]);
            }
            float A, B;
            upk2(ab0, A, B); na[0] = A;
            upk2(ab1, A, B); na[1] = fmaf(1.0f, B, A);
            upk2(ab2, A, B); na[2] = fmaf(2.0f, B, A);
            upk2(ab3, A, B); na[3] = fmaf(3.0f, B, A);
        }

        // ---- group B: outputs r = 4..7 (window base 28)
        {
            u64p ab0 = 0ULL, ab1 = 0ULL, ab2 = 0ULL, ab3 = 0ULL;
            u64p d0 = dup2(acc[3]);   // idx 27
            u64p d1 = dup2(acc[4]);
            u64p d2 = dup2(acc[5]);
            u64p d3 = dup2(acc[6]);
#pragma unroll
            for (int j = 1; j <= MTAPS; j++) {
                u64p k = kj[j - 1];
                ab0 = ffma2(d0, k, ab0);
                ab1 = ffma2(d1, k, ab1);
                ab2 = ffma2(d2, k, ab2);
                ab3 = ffma2(d3, k, ab3);
                d3 = d2; d2 = d1; d1 = d0;
                if (j < MTAPS) {
                    int idx = 27 - j;
                    d0 = (idx >= 24) ? dup2(acc[idx - 24]) : dup2(w[idx]);
                }
            }
            float A, B;
            upk2(ab0, A, B); na[4] = fmaf(4.0f, B, A);
            upk2(ab1, A, B); na[5] = fmaf(5.0f, B, A);
            upk2(ab2, A, B); na[6] = fmaf(6.0f, B, A);
            upk2(ab3, A, B); na[7] = fmaf(7.0f, B, A);
        }

#pragma unroll
        for (int r = 0; r < RPT; r++) {
            acc[r] = na[r];
            y[r]   = fmaf(na[r], fi, y[r]);
        }

        if (i < NSTAGES) {
            float4* st = (float4*)(nxt + PADZ + lp);
            float4 f0; f0.x = acc[0]; f0.y = acc[1]; f0.z = acc[2]; f0.w = acc[3];
            float4 f1; f1.x = acc[4]; f1.y = acc[5]; f1.z = acc[6]; f1.w = acc[7];
            st[0] = f0; st[1] = f1;
            __syncthreads();
            float* tmp = cur; cur = nxt; nxt = tmp;
        }
    }

    // ---- epilogue: out = y * exp(interp(mc[...,0])) ----
    if (lp >= HALO) {
        float* ob = out + b * TLEN;
#pragma unroll
        for (int r = 0; r < RPT; r++) {
            int tt = tbase + r;
            if (tt < TLEN) {
                float K = expf(fmaf(fmaf((float)r, invP, w0), dk, k0));
                ob[tt] = y[r] * K;
            }
        }
    }
}

extern "C" void kernel_launch(void* const* d_in, const int* in_sizes, int n_in,
                              void* d_out, int out_size)
{
    (void)in_sizes; (void)n_in; (void)out_size;
    const float* x   = (const float*)d_in[0];
    const float* mc  = (const float*)d_in[1];
    const float* a   = (const float*)d_in[2];
    const float* wts = (const float*)d_in[3];
    float* out = (float*)d_out;

    fir_taylor_kernel<<<BATCH * BPB, BLOCK>>>(x, mc, a, wts, out);
}